// round 7
// baseline (speedup 1.0000x reference)
#include <cuda_runtime.h>
#include <cstdint>

// dcn_56925496541545: 3x (sparse 9x9 neighbor-mean stencil -> convex combo -> sigmoid),
// output = x[:,0]. Inputs: d_in[0] = x [N,9] f32, d_in[1] = w1 [1] f32. Out: [N] f32.
//
// R6: packed f32x2 arithmetic (FFMA2/FADD2) -- each thread evaluates TWO
//     patches (t, t+256) with all stencil math on 2-wide packed floats,
//     halving FMA-pipe instructions. R3-style 4-stage cp.async ring
//     (256-patch stages) consumed in contiguous stage-pairs (512 patches).

#define THREADS 256
#define CHUNK_P 256                    // patches per cp.async stage
#define CHUNK_F (CHUNK_P * 9)          // 2304 floats = 9216 B
#define CHUNK_F4 (CHUNK_F / 4)         // 576
#define STAGES 4
#define CPB 8                          // chunks per block -> 2048 patches
#define PPB (CHUNK_P * CPB)

typedef unsigned long long u64;

// ---- packed f32x2 helpers (sm_100+ PTX) ----
__device__ __forceinline__ u64 pk2(float lo, float hi) {
    u64 r; asm("mov.b64 %0,{%1,%2};" : "=l"(r) : "f"(lo), "f"(hi)); return r;
}
__device__ __forceinline__ void upk2(u64 v, float& lo, float& hi) {
    asm("mov.b64 {%0,%1},%2;" : "=f"(lo), "=f"(hi) : "l"(v));
}
__device__ __forceinline__ u64 add2(u64 a, u64 b) {
    u64 r; asm("add.rn.f32x2 %0,%1,%2;" : "=l"(r) : "l"(a), "l"(b)); return r;
}
__device__ __forceinline__ u64 sub2(u64 a, u64 b) {
    u64 r; asm("sub.rn.f32x2 %0,%1,%2;" : "=l"(r) : "l"(a), "l"(b)); return r;
}
__device__ __forceinline__ u64 mul2(u64 a, u64 b) {
    u64 r; asm("mul.rn.f32x2 %0,%1,%2;" : "=l"(r) : "l"(a), "l"(b)); return r;
}
__device__ __forceinline__ u64 fma2(u64 a, u64 b, u64 c) {
    u64 r; asm("fma.rn.f32x2 %0,%1,%2,%3;" : "=l"(r) : "l"(a), "l"(b), "l"(c)); return r;
}

// sigmoid of both lanes: 0.5*tanh(t/2)+0.5 (caller pre-halved the argument)
__device__ __forceinline__ u64 sigmoid2(u64 t, u64 half2c) {
    float lo, hi, tl, th;
    upk2(t, lo, hi);
    asm("tanh.approx.f32 %0,%1;" : "=f"(tl) : "f"(lo));
    asm("tanh.approx.f32 %0,%1;" : "=f"(th) : "f"(hi));
    return fma2(pk2(tl, th), half2c, half2c);
}

// Packed 2-patch evaluation with DCE: iter1 all 9, iter2 {0,1,3,4}, iter3 {0}.
__device__ __forceinline__ u64 patch_eval2(const float* __restrict__ aA,
                                           const float* __restrict__ aB,
                                           u64 H1, u64 H3, u64 H5, u64 H8, u64 HALF2) {
    u64 a0 = pk2(aA[0], aB[0]), a1 = pk2(aA[1], aB[1]), a2 = pk2(aA[2], aB[2]),
        a3 = pk2(aA[3], aB[3]), a4 = pk2(aA[4], aB[4]), a5 = pk2(aA[5], aB[5]),
        a6 = pk2(aA[6], aB[6]), a7 = pk2(aA[7], aB[7]), a8 = pk2(aA[8], aB[8]);

    // ---- iteration 1 ----
    {
        u64 p14 = add2(a1, a4), p34 = add2(a3, a4), p45 = add2(a4, a5), p47 = add2(a4, a7);
        u64 q02 = add2(a0, a2), q06 = add2(a0, a6), q28 = add2(a2, a8), q68 = add2(a6, a8);
        u64 b00 = add2(p34, a1);
        u64 b02 = add2(p14, a5);
        u64 b20 = add2(p34, a7);
        u64 b22 = add2(p45, a7);
        u64 b01 = add2(add2(q02, p34), a5);
        u64 b10 = add2(add2(q06, p14), a7);
        u64 b12 = add2(add2(q28, p47), a1);
        u64 b21 = add2(add2(q68, p45), a3);
        u64 s   = add2(add2(add2(b01, a1), a7), q68);  // sum of all 9
        u64 b11 = sub2(s, a4);

        a0 = sigmoid2(fma2(H1, a0, mul2(H3, b00)), HALF2);
        a1 = sigmoid2(fma2(H1, a1, mul2(H5, b01)), HALF2);
        a2 = sigmoid2(fma2(H1, a2, mul2(H3, b02)), HALF2);
        a3 = sigmoid2(fma2(H1, a3, mul2(H5, b10)), HALF2);
        a4 = sigmoid2(fma2(H1, a4, mul2(H8, b11)), HALF2);
        a5 = sigmoid2(fma2(H1, a5, mul2(H5, b12)), HALF2);
        a6 = sigmoid2(fma2(H1, a6, mul2(H3, b20)), HALF2);
        a7 = sigmoid2(fma2(H1, a7, mul2(H5, b21)), HALF2);
        a8 = sigmoid2(fma2(H1, a8, mul2(H3, b22)), HALF2);
    }

    // ---- iteration 2: only {0,1,3,4} live ----
    u64 c0, c1, c3, c4;
    {
        u64 p34 = add2(a3, a4);
        u64 b00 = add2(p34, a1);
        u64 b01 = add2(add2(add2(a0, a2), p34), a5);
        u64 b10 = add2(add2(add2(a0, a6), add2(a1, a4)), a7);
        u64 s   = add2(add2(add2(add2(b01, a1), a7), a6), a8);
        u64 b11 = sub2(s, a4);

        c0 = sigmoid2(fma2(H1, a0, mul2(H3, b00)), HALF2);
        c1 = sigmoid2(fma2(H1, a1, mul2(H5, b01)), HALF2);
        c3 = sigmoid2(fma2(H1, a3, mul2(H5, b10)), HALF2);
        c4 = sigmoid2(fma2(H1, a4, mul2(H8, b11)), HALF2);
    }

    // ---- iteration 3: only element 0 ----
    u64 b00 = add2(add2(c1, c3), c4);
    return sigmoid2(fma2(H1, c0, mul2(H3, b00)), HALF2);
}

// Scalar path for tail blocks.
__device__ __forceinline__ float sigmoid_half_arg(float t_half) {
    float th; asm("tanh.approx.f32 %0, %1;" : "=f"(th) : "f"(t_half));
    return fmaf(0.5f, th, 0.5f);
}
__device__ __forceinline__ float patch_eval(const float* __restrict__ a,
                                            float h1, float h3, float h5, float h8) {
    float a0=a[0],a1=a[1],a2=a[2],a3=a[3],a4=a[4],a5=a[5],a6=a[6],a7=a[7],a8=a[8];
    {
        const float p14=a1+a4,p34=a3+a4,p45=a4+a5,p47=a4+a7;
        const float q02=a0+a2,q06=a0+a6,q28=a2+a8,q68=a6+a8;
        const float b00=p34+a1,b02=p14+a5,b20=p34+a7,b22=p45+a7;
        const float b01=(q02+p34)+a5,b10=(q06+p14)+a7,b12=(q28+p47)+a1,b21=(q68+p45)+a3;
        const float s=((b01+a1)+a7)+q68, b11=s-a4;
        a0=sigmoid_half_arg(fmaf(h1,a0,h3*b00)); a1=sigmoid_half_arg(fmaf(h1,a1,h5*b01));
        a2=sigmoid_half_arg(fmaf(h1,a2,h3*b02)); a3=sigmoid_half_arg(fmaf(h1,a3,h5*b10));
        a4=sigmoid_half_arg(fmaf(h1,a4,h8*b11)); a5=sigmoid_half_arg(fmaf(h1,a5,h5*b12));
        a6=sigmoid_half_arg(fmaf(h1,a6,h3*b20)); a7=sigmoid_half_arg(fmaf(h1,a7,h5*b21));
        a8=sigmoid_half_arg(fmaf(h1,a8,h3*b22));
    }
    float c0,c1,c3,c4;
    {
        const float p34=a3+a4, b00=p34+a1;
        const float b01=((a0+a2)+p34)+a5, b10=((a0+a6)+(a1+a4))+a7;
        const float s=(((b01+a1)+a7)+a6)+a8, b11=s-a4;
        c0=sigmoid_half_arg(fmaf(h1,a0,h3*b00)); c1=sigmoid_half_arg(fmaf(h1,a1,h5*b01));
        c3=sigmoid_half_arg(fmaf(h1,a3,h5*b10)); c4=sigmoid_half_arg(fmaf(h1,a4,h8*b11));
    }
    const float b00=(c1+c3)+c4;
    return sigmoid_half_arg(fmaf(h1,c0,h3*b00));
}

// Issue one 256-patch chunk into ring stage (full chunks only); always commits.
__device__ __forceinline__ void prefetch_chunk(const float4* __restrict__ x4,
                                               int chunk, int limit_chunks,
                                               uint32_t s_base, int stage, int tid) {
    if (chunk < limit_chunks) {
        const float4* g = x4 + (uint32_t)chunk * CHUNK_F4;
        const uint32_t sb = s_base + (uint32_t)stage * (CHUNK_F * 4u);
        int i = tid;
        asm volatile("cp.async.cg.shared.global [%0], [%1], 16;\n"
                     :: "r"(sb + i * 16u), "l"(g + i));
        i = tid + THREADS;
        asm volatile("cp.async.cg.shared.global [%0], [%1], 16;\n"
                     :: "r"(sb + i * 16u), "l"(g + i));
        if (tid < CHUNK_F4 - 2 * THREADS) {  // 64 threads carry the 3rd float4
            i = tid + 2 * THREADS;
            asm volatile("cp.async.cg.shared.global [%0], [%1], 16;\n"
                         :: "r"(sb + i * 16u), "l"(g + i));
        }
    }
    asm volatile("cp.async.commit_group;\n" ::: "memory");
}

__global__ __launch_bounds__(THREADS, 4)
void dcn_56925496541545_kernel(const float* __restrict__ x,
                               const float* __restrict__ w1p,
                               float* __restrict__ out,
                               int n)
{
    __shared__ float sx[STAGES * CHUNK_F];  // 36864 B

    const int tid = threadIdx.x;
    const int blockPatch0 = blockIdx.x * PPB;
    const uint32_t s_base = (uint32_t)__cvta_generic_to_shared(sx);

    const float w1 = __ldg(w1p);
    const float w2 = 1.0f - w1;
    const float h1 = 0.5f * w1;
    const float h3 = 0.5f * w2 * (1.0f / 3.0f);
    const float h5 = 0.5f * w2 * (1.0f / 5.0f);
    const float h8 = 0.5f * w2 * (1.0f / 8.0f);

    if (blockPatch0 + PPB <= n) {
        // ---- full block fast path: packed 2-patch evaluation ----
        const u64 H1 = pk2(h1, h1), H3 = pk2(h3, h3),
                  H5 = pk2(h5, h5), H8 = pk2(h8, h8), HALF2 = pk2(0.5f, 0.5f);

        const float4* x4 = reinterpret_cast<const float4*>(x);
        const int chunk0 = blockIdx.x * CPB;

        // prologue: fill all 4 stages
        prefetch_chunk(x4, chunk0 + 0, chunk0 + CPB, s_base, 0, tid);
        prefetch_chunk(x4, chunk0 + 1, chunk0 + CPB, s_base, 1, tid);
        prefetch_chunk(x4, chunk0 + 2, chunk0 + CPB, s_base, 2, tid);
        prefetch_chunk(x4, chunk0 + 3, chunk0 + CPB, s_base, 3, tid);

        #pragma unroll
        for (int i = 0; i < CPB / 2; ++i) {
            // chunks 2i, 2i+1 live in contiguous stages p, p+1
            asm volatile("cp.async.wait_group %0;\n" :: "n"(2) : "memory");
            __syncthreads();

            const int p = (i & 1) * 2;
            const float* st = &sx[p * CHUNK_F];
            const int basePatch = blockPatch0 + i * (2 * CHUNK_P);

            u64 r = patch_eval2(st + tid * 9, st + (tid + CHUNK_P) * 9,
                                H1, H3, H5, H8, HALF2);
            float rA, rB; upk2(r, rA, rB);
            out[basePatch + tid] = rA;
            out[basePatch + CHUNK_P + tid] = rB;

            __syncthreads();  // all warps done with stages p,p+1 before refill

            prefetch_chunk(x4, chunk0 + 2 * i + 4, chunk0 + CPB, s_base, p, tid);
            prefetch_chunk(x4, chunk0 + 2 * i + 5, chunk0 + CPB, s_base, p + 1, tid);
        }
    } else {
        // ---- tail block: scalar, direct global reads ----
        for (int p = blockPatch0 + tid; p < n; p += THREADS)
            out[p] = patch_eval(x + p * 9, h1, h3, h5, h8);
    }
}

extern "C" void kernel_launch(void* const* d_in, const int* in_sizes, int n_in,
                              void* d_out, int out_size) {
    const float* x   = (const float*)d_in[0];
    const float* w1  = (const float*)d_in[1];
    float* out       = (float*)d_out;
    const int n      = in_sizes[0] / 9;  // number of patches

    const int blocks = (int)(((long long)n + PPB - 1) / PPB);
    dcn_56925496541545_kernel<<<blocks, THREADS>>>(x, w1, out, n);
}

// round 8
// speedup vs baseline: 1.0904x; 1.0904x over previous
#include <cuda_runtime.h>
#include <cstdint>

// dcn_56925496541545: 3x (sparse 9x9 neighbor-mean stencil -> convex combo -> sigmoid),
// output = x[:,0]. Inputs: d_in[0] = x [N,9] f32, d_in[1] = w1 [1] f32. Out: [N] f32.
//
// R7: TMA bulk staging. Per block: 4 chunks of 256 patches, each loaded by a
//     single cp.async.bulk (9216 B) issued by thread 0, completed via mbarrier
//     complete_tx. No per-thread cp.async, no commit groups, and NO bar.sync
//     in the consume path -- consumers just mbarrier.try_wait their chunk.

#define THREADS 256
#define CHUNK_P 256                 // patches per chunk
#define CHUNK_F (CHUNK_P * 9)       // 2304 floats
#define CHUNK_BYTES (CHUNK_F * 4)   // 9216 B
#define CHUNKS 4
#define PPB (CHUNK_P * CHUNKS)      // 1024 patches per block

__device__ __forceinline__ float sigmoid_half_arg(float t_half) {
    // sigmoid(t) = 0.5*tanh(t/2) + 0.5 ; caller passes t/2 (halves folded into weights)
    float th;
    asm("tanh.approx.f32 %0, %1;" : "=f"(th) : "f"(t_half));
    return fmaf(0.5f, th, 0.5f);
}

// 3-iteration patch evaluation with dead-code elimination:
// iter1 keeps all 9, iter2 keeps {0,1,3,4}, iter3 keeps {0}.
__device__ __forceinline__ float patch_eval(const float* __restrict__ a,
                                            float h1, float h3, float h5, float h8) {
    float a0 = a[0], a1 = a[1], a2 = a[2],
          a3 = a[3], a4 = a[4], a5 = a[5],
          a6 = a[6], a7 = a[7], a8 = a[8];

    // ---- iteration 1: all 9 live ----
    {
        const float p14 = a1 + a4, p34 = a3 + a4, p45 = a4 + a5, p47 = a4 + a7;
        const float q02 = a0 + a2, q06 = a0 + a6, q28 = a2 + a8, q68 = a6 + a8;
        const float b00 = p34 + a1;
        const float b02 = p14 + a5;
        const float b20 = p34 + a7;
        const float b22 = p45 + a7;
        const float b01 = (q02 + p34) + a5;
        const float b10 = (q06 + p14) + a7;
        const float b12 = (q28 + p47) + a1;
        const float b21 = (q68 + p45) + a3;
        const float s   = ((b01 + a1) + a7) + q68;   // sum of all 9
        const float b11 = s - a4;

        a0 = sigmoid_half_arg(fmaf(h1, a0, h3 * b00));
        a1 = sigmoid_half_arg(fmaf(h1, a1, h5 * b01));
        a2 = sigmoid_half_arg(fmaf(h1, a2, h3 * b02));
        a3 = sigmoid_half_arg(fmaf(h1, a3, h5 * b10));
        a4 = sigmoid_half_arg(fmaf(h1, a4, h8 * b11));
        a5 = sigmoid_half_arg(fmaf(h1, a5, h5 * b12));
        a6 = sigmoid_half_arg(fmaf(h1, a6, h3 * b20));
        a7 = sigmoid_half_arg(fmaf(h1, a7, h5 * b21));
        a8 = sigmoid_half_arg(fmaf(h1, a8, h3 * b22));
    }

    // ---- iteration 2: only {0,1,3,4} live ----
    float c0, c1, c3, c4;
    {
        const float p34 = a3 + a4;
        const float b00 = p34 + a1;
        const float b01 = ((a0 + a2) + p34) + a5;
        const float b10 = ((a0 + a6) + (a1 + a4)) + a7;
        const float s   = (((b01 + a1) + a7) + a6) + a8;  // sum of all 9
        const float b11 = s - a4;

        c0 = sigmoid_half_arg(fmaf(h1, a0, h3 * b00));
        c1 = sigmoid_half_arg(fmaf(h1, a1, h5 * b01));
        c3 = sigmoid_half_arg(fmaf(h1, a3, h5 * b10));
        c4 = sigmoid_half_arg(fmaf(h1, a4, h8 * b11));
    }

    // ---- iteration 3: only element 0 consumed ----
    const float b00 = (c1 + c3) + c4;
    return sigmoid_half_arg(fmaf(h1, c0, h3 * b00));
}

__device__ __forceinline__ void mbar_wait(uint32_t mbar, uint32_t parity) {
    uint32_t done;
    asm volatile(
        "{\n\t"
        ".reg .pred p;\n\t"
        "mbarrier.try_wait.parity.acquire.cta.shared::cta.b64 p, [%1], %2;\n\t"
        "selp.b32 %0, 1, 0, p;\n\t"
        "}"
        : "=r"(done) : "r"(mbar), "r"(parity) : "memory");
    if (!done) {
        asm volatile(
            "{\n\t"
            ".reg .pred P1;\n\t"
            "W_%=:\n\t"
            "mbarrier.try_wait.parity.acquire.cta.shared::cta.b64 P1, [%0], %1, 0x989680;\n\t"
            "@P1 bra.uni D_%=;\n\t"
            "bra.uni W_%=;\n\t"
            "D_%=:\n\t"
            "}"
            :: "r"(mbar), "r"(parity) : "memory");
    }
}

__global__ __launch_bounds__(THREADS, 6)
void dcn_56925496541545_kernel(const float* __restrict__ x,
                               const float* __restrict__ w1p,
                               float* __restrict__ out,
                               int n)
{
    __shared__ __align__(128) float sx[CHUNKS * CHUNK_F];        // 36864 B
    __shared__ __align__(8)   unsigned long long mbar[CHUNKS];

    const int tid = threadIdx.x;
    const int blockPatch0 = blockIdx.x * PPB;

    const float w1 = __ldg(w1p);
    const float w2 = 1.0f - w1;
    const float h1 = 0.5f * w1;
    const float h3 = 0.5f * w2 * (1.0f / 3.0f);
    const float h5 = 0.5f * w2 * (1.0f / 5.0f);
    const float h8 = 0.5f * w2 * (1.0f / 8.0f);

    if (blockPatch0 + PPB <= n) {
        // ---- full-block fast path: TMA bulk staging ----
        const uint32_t s_base = (uint32_t)__cvta_generic_to_shared(sx);
        const uint32_t m_base = (uint32_t)__cvta_generic_to_shared(mbar);

        if (tid == 0) {
            #pragma unroll
            for (int c = 0; c < CHUNKS; ++c)
                asm volatile("mbarrier.init.shared.b64 [%0], %1;"
                             :: "r"(m_base + c * 8u), "r"(1) : "memory");
        }
        __syncthreads();   // publish mbarrier init to all warps

        if (tid == 0) {
            const char* src = reinterpret_cast<const char*>(x)
                            + (size_t)blockPatch0 * 36;   // 9 floats * 4B
            #pragma unroll
            for (int c = 0; c < CHUNKS; ++c) {
                const uint32_t mb = m_base + c * 8u;
                asm volatile("mbarrier.arrive.expect_tx.shared.b64 _, [%0], %1;"
                             :: "r"(mb), "r"(CHUNK_BYTES) : "memory");
                asm volatile(
                    "cp.async.bulk.shared::cta.global.mbarrier::complete_tx::bytes "
                    "[%0], [%1], %2, [%3];"
                    :: "r"(s_base + c * (uint32_t)CHUNK_BYTES),
                       "l"(src + (size_t)c * CHUNK_BYTES),
                       "r"(CHUNK_BYTES), "r"(mb)
                    : "memory");
            }
        }

        // ---- consume: per-chunk mbarrier wait, no block barriers ----
        #pragma unroll
        for (int c = 0; c < CHUNKS; ++c) {
            mbar_wait(m_base + c * 8u, 0u);
            const float* a = &sx[c * CHUNK_F + tid * 9];  // stride-9: conflict-free
            out[blockPatch0 + c * CHUNK_P + tid] = patch_eval(a, h1, h3, h5, h8);
        }
    } else {
        // ---- tail block: scalar, direct global reads ----
        for (int p = blockPatch0 + tid; p < n; p += THREADS)
            out[p] = patch_eval(x + p * 9, h1, h3, h5, h8);
    }
}

extern "C" void kernel_launch(void* const* d_in, const int* in_sizes, int n_in,
                              void* d_out, int out_size) {
    const float* x   = (const float*)d_in[0];
    const float* w1  = (const float*)d_in[1];
    float* out       = (float*)d_out;
    const int n      = in_sizes[0] / 9;  // number of patches

    const int blocks = (int)(((long long)n + PPB - 1) / PPB);
    dcn_56925496541545_kernel<<<blocks, THREADS>>>(x, w1, out, n);
}

// round 9
// speedup vs baseline: 1.1515x; 1.0560x over previous
#include <cuda_runtime.h>
#include <cstdint>

// dcn_56925496541545: 3x (sparse 9x9 neighbor-mean stencil -> convex combo -> sigmoid),
// output = x[:,0]. Inputs: d_in[0] = x [N,9] f32, d_in[1] = w1 [1] f32. Out: [N] f32.
//
// R8: R3 skeleton (4-stage pipelined cp.async, 256-patch chunks) + tanh-space
//     algebra: post-sigmoid affine (0.5*tanh+0.5) folded into next iteration's
//     weights, deleting 13 of 14 post-tanh FMAs. 68 FMA-pipe ops/patch (was 81).
//     Exact transformation; DCE keeps iter2={0,1,3,4}, iter3={0}.

#define THREADS 256
#define IPT 4
#define PPB (THREADS * IPT)               // patches per block = 1024
#define F4_PER_CHUNK ((THREADS * 9) / 4)  // 576 float4 per 256-patch chunk

__device__ __forceinline__ float tanh_fast(float t) {
    float th;
    asm("tanh.approx.f32 %0, %1;" : "=f"(th) : "f"(t));
    return th;
}

// 3-iteration evaluation in tanh-space.
//  iter1: u_r = tanh(h1*a_r + h_len*b_r)            (h's carry the 0.5 and 1/len)
//  iter2: v_r = tanh(g1*u_r + g_len*(sum nbr u) + 0.25)
//  iter3: out = 0.5*tanh(g1*v0 + g3*(v1+v3+v4) + 0.25) + 0.5
// where g1 = w1/4, g_len = w2/(4*len).
__device__ __forceinline__ float patch_eval(const float* __restrict__ a,
                                            float h1, float h3, float h5, float h8,
                                            float g1, float g3, float g5, float g8) {
    const float a0 = a[0], a1 = a[1], a2 = a[2],
                a3 = a[3], a4 = a[4], a5 = a[5],
                a6 = a[6], a7 = a[7], a8 = a[8];

    // ---- iteration 1 (a-space -> u-space), all 9 live ----
    float u0, u1, u2, u3, u4, u5, u6, u7, u8;
    {
        const float p14 = a1 + a4, p34 = a3 + a4, p45 = a4 + a5, p47 = a4 + a7;
        const float q02 = a0 + a2, q06 = a0 + a6, q28 = a2 + a8, q68 = a6 + a8;
        const float b00 = p34 + a1;
        const float b02 = p14 + a5;
        const float b20 = p34 + a7;
        const float b22 = p45 + a7;
        const float b01 = (q02 + p34) + a5;
        const float b10 = (q06 + p14) + a7;
        const float b12 = (q28 + p47) + a1;
        const float b21 = (q68 + p45) + a3;
        const float s   = ((b01 + a1) + a7) + q68;   // sum of all 9
        const float b11 = s - a4;

        u0 = tanh_fast(fmaf(h1, a0, h3 * b00));
        u1 = tanh_fast(fmaf(h1, a1, h5 * b01));
        u2 = tanh_fast(fmaf(h1, a2, h3 * b02));
        u3 = tanh_fast(fmaf(h1, a3, h5 * b10));
        u4 = tanh_fast(fmaf(h1, a4, h8 * b11));
        u5 = tanh_fast(fmaf(h1, a5, h5 * b12));
        u6 = tanh_fast(fmaf(h1, a6, h3 * b20));
        u7 = tanh_fast(fmaf(h1, a7, h5 * b21));
        u8 = tanh_fast(fmaf(h1, a8, h3 * b22));
    }

    // ---- iteration 2 (u-space -> v-space), only {0,1,3,4} live ----
    float v0, v1, v3, v4;
    {
        const float p34 = u3 + u4;
        const float b00 = p34 + u1;
        const float b01 = ((u0 + u2) + p34) + u5;
        const float b10 = ((u0 + u6) + (u1 + u4)) + u7;
        const float s   = (((b01 + u1) + u7) + u6) + u8;  // sum of all 9
        const float b11 = s - u4;

        v0 = tanh_fast(fmaf(g1, u0, fmaf(g3, b00, 0.25f)));
        v1 = tanh_fast(fmaf(g1, u1, fmaf(g5, b01, 0.25f)));
        v3 = tanh_fast(fmaf(g1, u3, fmaf(g5, b10, 0.25f)));
        v4 = tanh_fast(fmaf(g1, u4, fmaf(g8, b11, 0.25f)));
    }

    // ---- iteration 3: only element 0; final sigmoid reconstructed ----
    const float b00 = (v1 + v3) + v4;
    const float t   = tanh_fast(fmaf(g1, v0, fmaf(g3, b00, 0.25f)));
    return fmaf(0.5f, t, 0.5f);
}

__global__ __launch_bounds__(THREADS, 3)
void dcn_56925496541545_kernel(const float* __restrict__ x,
                               const float* __restrict__ w1p,
                               float* __restrict__ out,
                               int n)  // number of patches
{
    __shared__ float sx[PPB * 9];  // 36864 B

    const long long patch0 = (long long)blockIdx.x * PPB;
    const long long baseF  = patch0 * 9;
    const int tid = threadIdx.x;

    const float w1 = __ldg(w1p);   // issue early; overlaps with cp.async setup
    const bool full = (patch0 + PPB <= (long long)n);

    const uint32_t s_base = (uint32_t)__cvta_generic_to_shared(sx);

    if (full) {
        // ---- issue 4 commit groups, one per 256-patch chunk (9216 B each) ----
        const float4* g = reinterpret_cast<const float4*>(x + baseF);  // 16B aligned
        #pragma unroll
        for (int c = 0; c < IPT; ++c) {
            const int b4 = c * F4_PER_CHUNK;
            {
                int i = b4 + tid;
                asm volatile("cp.async.cg.shared.global [%0], [%1], 16;\n"
                             :: "r"(s_base + i * 16u), "l"(g + i));
            }
            {
                int i = b4 + tid + THREADS;
                asm volatile("cp.async.cg.shared.global [%0], [%1], 16;\n"
                             :: "r"(s_base + i * 16u), "l"(g + i));
            }
            if (tid < F4_PER_CHUNK - 2 * THREADS) {   // 64 threads carry the 3rd float4
                int i = b4 + tid + 2 * THREADS;
                asm volatile("cp.async.cg.shared.global [%0], [%1], 16;\n"
                             :: "r"(s_base + i * 16u), "l"(g + i));
            }
            asm volatile("cp.async.commit_group;\n" ::: "memory");
        }
    } else {
        // tail block: guarded scalar loads, single barrier, guarded compute below
        const long long totalF = (long long)n * 9;
        for (int i = tid; i < PPB * 9; i += THREADS) {
            long long gidx = baseF + i;
            sx[i] = (gidx < totalF) ? x[gidx] : 0.0f;
        }
    }

    const float w2 = 1.0f - w1;
    // iter1 weights (0.5 and 1/len folded)
    const float h1 = 0.5f * w1;
    const float h3 = 0.5f * w2 * (1.0f / 3.0f);
    const float h5 = 0.5f * w2 * (1.0f / 5.0f);
    const float h8 = 0.5f * w2 * (1.0f / 8.0f);
    // tanh-space weights for iters 2,3: g1 = w1/4, g_len = w2/(4*len)
    const float g1 = 0.25f * w1;
    const float g3 = 0.25f * w2 * (1.0f / 3.0f);
    const float g5 = 0.25f * w2 * (1.0f / 5.0f);
    const float g8 = 0.25f * w2 * (1.0f / 8.0f);

    if (full) {
        // ---- pipelined consume: chunk c computes while chunks c+1.. are in flight ----
        #define CONSUME_CHUNK(C, WAITN)                                              \
            {                                                                        \
                asm volatile("cp.async.wait_group %0;\n" :: "n"(WAITN) : "memory");  \
                __syncthreads();                                                     \
                const int lp = tid + (C) * THREADS;                                  \
                out[patch0 + lp] = patch_eval(&sx[lp * 9],                           \
                                              h1, h3, h5, h8, g1, g3, g5, g8);       \
            }
        CONSUME_CHUNK(0, 3)
        CONSUME_CHUNK(1, 2)
        CONSUME_CHUNK(2, 1)
        CONSUME_CHUNK(3, 0)
        #undef CONSUME_CHUNK
    } else {
        __syncthreads();
        #pragma unroll
        for (int c = 0; c < IPT; ++c) {
            const int lp = tid + c * THREADS;
            const long long p = patch0 + lp;
            if (p < (long long)n)
                out[p] = patch_eval(&sx[lp * 9], h1, h3, h5, h8, g1, g3, g5, g8);
        }
    }
}

extern "C" void kernel_launch(void* const* d_in, const int* in_sizes, int n_in,
                              void* d_out, int out_size) {
    const float* x   = (const float*)d_in[0];
    const float* w1  = (const float*)d_in[1];
    float* out       = (float*)d_out;
    const int n      = in_sizes[0] / 9;  // number of patches

    const int blocks = (int)(((long long)n + PPB - 1) / PPB);
    dcn_56925496541545_kernel<<<blocks, THREADS>>>(x, w1, out, n);
}